// round 1
// baseline (speedup 1.0000x reference)
#include <cuda_runtime.h>
#include <math.h>

#define NTOK 8192
#define DM   1024
#define HID  4096
#define NE   7

#define BM 128
#define BN 64
#define BK 16
#define SA_STRIDE 20   // BK + 4  (conflict-free A fragment LDS)
#define SB_STRIDE 72   // BN + 8  (conflict-free B fragment LDS, 16B-aligned rows)

// ---------------- device scratch (static, no allocations) ----------------
__device__ int   g_cnt[NE];
__device__ int   g_off[NE + 1];
__device__ int   g_tok[NE * NTOK];
__device__ float g_wt [NE * NTOK];
__device__ int   g_dst[NE * NTOK];
__device__ float g_h[24576u * HID];        // compact hidden activations (402 MB)
__device__ float g_y[NTOK * 3u * DM];      // per-slot down outputs (100 MB)

// ---------------- helpers ----------------
__device__ __forceinline__ unsigned f2tf(float f) {
    unsigned u;
    asm("cvt.rna.tf32.f32 %0, %1;" : "=r"(u) : "f"(f));
    return u;
}

__device__ __forceinline__ void mma_tf32(float c[4], const unsigned a[4], const unsigned b[2]) {
    asm volatile(
        "mma.sync.aligned.m16n8k8.row.col.f32.tf32.tf32.f32 "
        "{%0,%1,%2,%3},{%4,%5,%6,%7},{%8,%9},{%0,%1,%2,%3};"
        : "+f"(c[0]), "+f"(c[1]), "+f"(c[2]), "+f"(c[3])
        : "r"(a[0]), "r"(a[1]), "r"(a[2]), "r"(a[3]), "r"(b[0]), "r"(b[1]));
}

// ---------------- kernel 1: reset counters ----------------
__global__ void zero_kernel() {
    if (threadIdx.x < NE) g_cnt[threadIdx.x] = 0;
}

// ---------------- kernel 2: router (one warp per token) ----------------
__global__ void __launch_bounds__(256) router_kernel(const float* __restrict__ x,
                                                     const float* __restrict__ rw) {
    __shared__ float srw[NE * DM];
    for (int i = threadIdx.x; i < NE * DM; i += blockDim.x) srw[i] = rw[i];
    __syncthreads();

    int warp = (blockIdx.x * blockDim.x + threadIdx.x) >> 5;
    int lane = threadIdx.x & 31;
    if (warp >= NTOK) return;

    const float* xr = x + (size_t)warp * DM;
    float acc[NE];
#pragma unroll
    for (int e = 0; e < NE; e++) acc[e] = 0.f;
    for (int k = lane; k < DM; k += 32) {
        float xv = xr[k];
#pragma unroll
        for (int e = 0; e < NE; e++) acc[e] += xv * srw[e * DM + k];
    }
#pragma unroll
    for (int e = 0; e < NE; e++) {
#pragma unroll
        for (int o = 16; o > 0; o >>= 1) acc[e] += __shfl_xor_sync(0xffffffffu, acc[e], o);
    }
    if (lane == 0) {
        int i1 = 0; float v1 = acc[0];
#pragma unroll
        for (int e = 1; e < NE; e++) if (acc[e] > v1) { v1 = acc[e]; i1 = e; }
        int i2 = -1; float v2 = -1e30f;
#pragma unroll
        for (int e = 0; e < NE; e++) if (e != i1 && acc[e] > v2) { v2 = acc[e]; i2 = e; }
        float w1 = 1.f / (1.f + expf(v2 - v1));
        float w2 = 1.f - w1;
        int p1 = atomicAdd(&g_cnt[i1], 1);
        g_tok[i1 * NTOK + p1] = warp;
        g_wt [i1 * NTOK + p1] = w1;
        g_dst[i1 * NTOK + p1] = warp * 3 + 0;
        int p2 = atomicAdd(&g_cnt[i2], 1);
        g_tok[i2 * NTOK + p2] = warp;
        g_wt [i2 * NTOK + p2] = w2;
        g_dst[i2 * NTOK + p2] = warp * 3 + 1;
    }
}

// ---------------- kernel 3: offsets scan ----------------
__global__ void scan_kernel() {
    if (threadIdx.x == 0) {
        int s = 0;
        for (int e = 0; e < NE; e++) { g_off[e] = s; s += g_cnt[e]; }
        g_off[NE] = s;   // == 16384
    }
}

// ---------------- kernel 4: grouped up-GEMM (gate & up fused, SiLU*u epilogue) ----------------
__global__ void __launch_bounds__(256) up_kernel(const float* __restrict__ x,
                                                 const float* __restrict__ wg,
                                                 const float* __restrict__ wu,
                                                 const float* __restrict__ swg,
                                                 const float* __restrict__ swu) {
    int grp = blockIdx.z;
    int cnt, hbase;
    const float *pg, *pu;
    if (grp < NE) {
        cnt = g_cnt[grp]; hbase = g_off[grp];
        pg = wg + (size_t)grp * DM * HID;
        pu = wu + (size_t)grp * DM * HID;
    } else {
        cnt = NTOK; hbase = 16384; pg = swg; pu = swu;
    }
    int mt0 = blockIdx.x * BM;
    if (mt0 >= cnt) return;
    int n0 = blockIdx.y * BN;

    __shared__ __align__(16) unsigned sA [2][BM * SA_STRIDE];
    __shared__ __align__(16) unsigned sBg[2][BK * SB_STRIDE];
    __shared__ __align__(16) unsigned sBu[2][BK * SB_STRIDE];

    int tid = threadIdx.x;
    int rA0 = tid >> 2, cA = (tid & 3) * 4;
    int rA1 = rA0 + 64;
    int lr0 = mt0 + rA0, lr1 = mt0 + rA1;
    int tok0, tok1;
    if (grp < NE) {
        tok0 = (lr0 < cnt) ? g_tok[grp * NTOK + lr0] : 0;
        tok1 = (lr1 < cnt) ? g_tok[grp * NTOK + lr1] : 0;
    } else {
        tok0 = (lr0 < cnt) ? lr0 : 0;
        tok1 = (lr1 < cnt) ? lr1 : 0;
    }
    const float* a0p = x + (size_t)tok0 * DM + cA;
    const float* a1p = x + (size_t)tok1 * DM + cA;

    int kB = tid >> 4, nB = (tid & 15) * 4;
    const float* bgp = pg + (size_t)kB * HID + n0 + nB;
    const float* bup = pu + (size_t)kB * HID + n0 + nB;

    float accG[2][4][4], accU[2][4][4];
#pragma unroll
    for (int a = 0; a < 2; a++)
#pragma unroll
        for (int b = 0; b < 4; b++)
#pragma unroll
            for (int c = 0; c < 4; c++) { accG[a][b][c] = 0.f; accU[a][b][c] = 0.f; }

    int warp = tid >> 5, lane = tid & 31;
    int wm = (warp & 3) * 32;
    int wn = (warp >> 2) * 32;
    int gid = lane >> 2, tig = lane & 3;

    float4 ra0, ra1, rbg, rbu;
    ra0 = *(const float4*)(a0p);
    ra1 = *(const float4*)(a1p);
    rbg = *(const float4*)(bgp);
    rbu = *(const float4*)(bup);
    {
        unsigned* pA = &sA[0][rA0 * SA_STRIDE + cA];
        pA[0] = f2tf(ra0.x); pA[1] = f2tf(ra0.y); pA[2] = f2tf(ra0.z); pA[3] = f2tf(ra0.w);
        pA = &sA[0][rA1 * SA_STRIDE + cA];
        pA[0] = f2tf(ra1.x); pA[1] = f2tf(ra1.y); pA[2] = f2tf(ra1.z); pA[3] = f2tf(ra1.w);
        uint4 t;
        t.x = f2tf(rbg.x); t.y = f2tf(rbg.y); t.z = f2tf(rbg.z); t.w = f2tf(rbg.w);
        *(uint4*)&sBg[0][kB * SB_STRIDE + nB] = t;
        t.x = f2tf(rbu.x); t.y = f2tf(rbu.y); t.z = f2tf(rbu.z); t.w = f2tf(rbu.w);
        *(uint4*)&sBu[0][kB * SB_STRIDE + nB] = t;
    }
    __syncthreads();

    const int NK = DM / BK;
    for (int kt = 0; kt < NK; kt++) {
        int s = kt & 1;
        if (kt + 1 < NK) {
            size_t ko = (size_t)(kt + 1) * BK;
            ra0 = *(const float4*)(a0p + ko);
            ra1 = *(const float4*)(a1p + ko);
            rbg = *(const float4*)(bgp + ko * HID);
            rbu = *(const float4*)(bup + ko * HID);
        }
#pragma unroll
        for (int ks = 0; ks < 2; ks++) {
            int k0 = ks * 8;
            unsigned af[2][4];
#pragma unroll
            for (int mt = 0; mt < 2; mt++) {
                int rb = wm + mt * 16 + gid;
                af[mt][0] = sA[s][rb * SA_STRIDE + k0 + tig];
                af[mt][1] = sA[s][(rb + 8) * SA_STRIDE + k0 + tig];
                af[mt][2] = sA[s][rb * SA_STRIDE + k0 + 4 + tig];
                af[mt][3] = sA[s][(rb + 8) * SA_STRIDE + k0 + 4 + tig];
            }
#pragma unroll
            for (int nt = 0; nt < 4; nt++) {
                int cb = wn + nt * 8 + gid;
                unsigned bg[2], bu[2];
                bg[0] = sBg[s][(k0 + tig) * SB_STRIDE + cb];
                bg[1] = sBg[s][(k0 + 4 + tig) * SB_STRIDE + cb];
                bu[0] = sBu[s][(k0 + tig) * SB_STRIDE + cb];
                bu[1] = sBu[s][(k0 + 4 + tig) * SB_STRIDE + cb];
#pragma unroll
                for (int mt = 0; mt < 2; mt++) {
                    mma_tf32(accG[mt][nt], af[mt], bg);
                    mma_tf32(accU[mt][nt], af[mt], bu);
                }
            }
        }
        if (kt + 1 < NK) {
            int s2 = s ^ 1;
            unsigned* pA = &sA[s2][rA0 * SA_STRIDE + cA];
            pA[0] = f2tf(ra0.x); pA[1] = f2tf(ra0.y); pA[2] = f2tf(ra0.z); pA[3] = f2tf(ra0.w);
            pA = &sA[s2][rA1 * SA_STRIDE + cA];
            pA[0] = f2tf(ra1.x); pA[1] = f2tf(ra1.y); pA[2] = f2tf(ra1.z); pA[3] = f2tf(ra1.w);
            uint4 t;
            t.x = f2tf(rbg.x); t.y = f2tf(rbg.y); t.z = f2tf(rbg.z); t.w = f2tf(rbg.w);
            *(uint4*)&sBg[s2][kB * SB_STRIDE + nB] = t;
            t.x = f2tf(rbu.x); t.y = f2tf(rbu.y); t.z = f2tf(rbu.z); t.w = f2tf(rbu.w);
            *(uint4*)&sBu[s2][kB * SB_STRIDE + nB] = t;
        }
        __syncthreads();
    }

    // epilogue: h = silu(g) * u
#pragma unroll
    for (int mt = 0; mt < 2; mt++) {
#pragma unroll
        for (int i = 0; i < 4; i++) {
            int row = wm + mt * 16 + gid + ((i & 2) ? 8 : 0);
            int lr = mt0 + row;
            if (lr >= cnt) continue;
            size_t base = (size_t)(hbase + lr) * HID + n0 + wn;
#pragma unroll
            for (int nt = 0; nt < 4; nt++) {
                float g = accG[mt][nt][i], u = accU[mt][nt][i];
                float h = g * u / (1.f + expf(-g));
                g_h[base + nt * 8 + tig * 2 + (i & 1)] = h;
            }
        }
    }
}

// ---------------- kernel 5: grouped down-GEMM (weighted, deterministic slots) ----------------
__global__ void __launch_bounds__(256) down_kernel(const float* __restrict__ wd,
                                                   const float* __restrict__ swd) {
    int grp = blockIdx.z;
    int cnt, hbase;
    const float* pd;
    if (grp < NE) { cnt = g_cnt[grp]; hbase = g_off[grp]; pd = wd + (size_t)grp * HID * DM; }
    else          { cnt = NTOK;       hbase = 16384;      pd = swd; }
    int mt0 = blockIdx.x * BM;
    if (mt0 >= cnt) return;
    int n0 = blockIdx.y * BN;

    __shared__ __align__(16) unsigned sA[2][BM * SA_STRIDE];
    __shared__ __align__(16) unsigned sB[2][BK * SB_STRIDE];

    int tid = threadIdx.x;
    int rA0 = tid >> 2, cA = (tid & 3) * 4;
    int rA1 = rA0 + 64;
    int lr0 = mt0 + rA0; if (lr0 >= cnt) lr0 = mt0;
    int lr1 = mt0 + rA1; if (lr1 >= cnt) lr1 = mt0;
    const float* a0p = g_h + (size_t)(hbase + lr0) * HID + cA;
    const float* a1p = g_h + (size_t)(hbase + lr1) * HID + cA;

    int kB = tid >> 4, nB = (tid & 15) * 4;
    const float* bp = pd + (size_t)kB * DM + n0 + nB;

    float acc[2][4][4];
#pragma unroll
    for (int a = 0; a < 2; a++)
#pragma unroll
        for (int b = 0; b < 4; b++)
#pragma unroll
            for (int c = 0; c < 4; c++) acc[a][b][c] = 0.f;

    int warp = tid >> 5, lane = tid & 31;
    int wm = (warp & 3) * 32;
    int wn = (warp >> 2) * 32;
    int gid = lane >> 2, tig = lane & 3;

    float4 ra0, ra1, rb;
    ra0 = *(const float4*)(a0p);
    ra1 = *(const float4*)(a1p);
    rb  = *(const float4*)(bp);
    {
        unsigned* pA = &sA[0][rA0 * SA_STRIDE + cA];
        pA[0] = f2tf(ra0.x); pA[1] = f2tf(ra0.y); pA[2] = f2tf(ra0.z); pA[3] = f2tf(ra0.w);
        pA = &sA[0][rA1 * SA_STRIDE + cA];
        pA[0] = f2tf(ra1.x); pA[1] = f2tf(ra1.y); pA[2] = f2tf(ra1.z); pA[3] = f2tf(ra1.w);
        uint4 t;
        t.x = f2tf(rb.x); t.y = f2tf(rb.y); t.z = f2tf(rb.z); t.w = f2tf(rb.w);
        *(uint4*)&sB[0][kB * SB_STRIDE + nB] = t;
    }
    __syncthreads();

    const int NK = HID / BK;
    for (int kt = 0; kt < NK; kt++) {
        int s = kt & 1;
        if (kt + 1 < NK) {
            size_t ko = (size_t)(kt + 1) * BK;
            ra0 = *(const float4*)(a0p + ko);
            ra1 = *(const float4*)(a1p + ko);
            rb  = *(const float4*)(bp + ko * DM);
        }
#pragma unroll
        for (int ks = 0; ks < 2; ks++) {
            int k0 = ks * 8;
            unsigned af[2][4];
#pragma unroll
            for (int mt = 0; mt < 2; mt++) {
                int rbw = wm + mt * 16 + gid;
                af[mt][0] = sA[s][rbw * SA_STRIDE + k0 + tig];
                af[mt][1] = sA[s][(rbw + 8) * SA_STRIDE + k0 + tig];
                af[mt][2] = sA[s][rbw * SA_STRIDE + k0 + 4 + tig];
                af[mt][3] = sA[s][(rbw + 8) * SA_STRIDE + k0 + 4 + tig];
            }
#pragma unroll
            for (int nt = 0; nt < 4; nt++) {
                int cb = wn + nt * 8 + gid;
                unsigned bf[2];
                bf[0] = sB[s][(k0 + tig) * SB_STRIDE + cb];
                bf[1] = sB[s][(k0 + 4 + tig) * SB_STRIDE + cb];
#pragma unroll
                for (int mt = 0; mt < 2; mt++) mma_tf32(acc[mt][nt], af[mt], bf);
            }
        }
        if (kt + 1 < NK) {
            int s2 = s ^ 1;
            unsigned* pA = &sA[s2][rA0 * SA_STRIDE + cA];
            pA[0] = f2tf(ra0.x); pA[1] = f2tf(ra0.y); pA[2] = f2tf(ra0.z); pA[3] = f2tf(ra0.w);
            pA = &sA[s2][rA1 * SA_STRIDE + cA];
            pA[0] = f2tf(ra1.x); pA[1] = f2tf(ra1.y); pA[2] = f2tf(ra1.z); pA[3] = f2tf(ra1.w);
            uint4 t;
            t.x = f2tf(rb.x); t.y = f2tf(rb.y); t.z = f2tf(rb.z); t.w = f2tf(rb.w);
            *(uint4*)&sB[s2][kB * SB_STRIDE + nB] = t;
        }
        __syncthreads();
    }

    // epilogue: y[dst] = wt * acc
    int   dsts[4]; float wts[4]; int valid[4];
    int   rws[4] = { wm + gid, wm + gid + 8, wm + 16 + gid, wm + 24 + gid };
#pragma unroll
    for (int j = 0; j < 4; j++) {
        int lr = mt0 + rws[j];
        valid[j] = (lr < cnt);
        int lc = valid[j] ? lr : mt0;
        if (grp < NE) { int q = grp * NTOK + lc; dsts[j] = g_dst[q]; wts[j] = g_wt[q]; }
        else          { dsts[j] = lc * 3 + 2;    wts[j] = 1.f; }
    }
#pragma unroll
    for (int mt = 0; mt < 2; mt++)
#pragma unroll
        for (int i = 0; i < 4; i++) {
            int j = mt * 2 + ((i & 2) ? 1 : 0);
            if (!valid[j]) continue;
#pragma unroll
            for (int nt = 0; nt < 4; nt++)
                g_y[(size_t)dsts[j] * DM + n0 + wn + nt * 8 + tig * 2 + (i & 1)] = wts[j] * acc[mt][nt][i];
        }
}

// ---------------- kernel 6: combine ----------------
__global__ void combine_kernel(float* __restrict__ out) {
    int i = blockIdx.x * blockDim.x + threadIdx.x;
    if (i >= NTOK * DM) return;
    int n = i / DM, c = i % DM;
    size_t b = (size_t)n * 3 * DM + c;
    out[i] = g_y[b] + g_y[b + DM] + g_y[b + 2 * DM];
}

// ---------------- launch ----------------
extern "C" void kernel_launch(void* const* d_in, const int* in_sizes, int n_in,
                              void* d_out, int out_size) {
    const float* x   = (const float*)d_in[0];
    const float* rw  = (const float*)d_in[1];
    const float* wg  = (const float*)d_in[2];
    const float* wu  = (const float*)d_in[3];
    const float* wd  = (const float*)d_in[4];
    const float* swg = (const float*)d_in[5];
    const float* swu = (const float*)d_in[6];
    const float* swd = (const float*)d_in[7];
    float* out = (float*)d_out;

    zero_kernel<<<1, 32>>>();
    router_kernel<<<NTOK / 8, 256>>>(x, rw);
    scan_kernel<<<1, 32>>>();
    dim3 gu(NTOK / BM, HID / BN, 8);   // (64, 64, 8)
    up_kernel<<<gu, 256>>>(x, wg, wu, swg, swu);
    dim3 gd(NTOK / BM, DM / BN, 8);    // (64, 16, 8)
    down_kernel<<<gd, 256>>>(wd, swd);
    combine_kernel<<<(NTOK * DM) / 256, 256>>>(out);
}

// round 3
// speedup vs baseline: 1.2149x; 1.2149x over previous
#include <cuda_runtime.h>
#include <cstdint>
#include <math.h>

#define NTOK 8192
#define DM   1024
#define HID  4096
#define NE   7

#define BM 128
#define BK 16
#define STAGES 4

// up-kernel stage layout (floats): A[128][20] ; Bg[16][72] ; Bu[16][72]
#define UP_SA    20
#define UP_SB    72
#define UP_A_OFF 0
#define UP_BG_OFF 10240
#define UP_BU_OFF 14848
#define UP_ST    19456          // bytes per stage

// down-kernel stage layout: A[128][20] ; B[16][136]
#define DN_SA    20
#define DN_SB    136
#define DN_A_OFF 0
#define DN_B_OFF 10240
#define DN_ST    18944

// ---------------- device scratch (static, no allocations) ----------------
__device__ int   g_cnt[NE];
__device__ int   g_off[NE + 1];
__device__ int   g_tok[NE * NTOK];
__device__ float g_wt [NE * NTOK];
__device__ int   g_dst[NE * NTOK];
__device__ float g_h[24576u * HID];            // compact hidden activations (tf32-rounded)
__device__ float g_y[NTOK * 3u * DM];          // per-slot down outputs
// tf32-pre-rounded copies of inputs
__device__ float g_cwg[NE * DM * HID];
__device__ float g_cwu[NE * DM * HID];
__device__ float g_cwd[NE * HID * DM];
__device__ float g_csg[DM * HID];
__device__ float g_csu[DM * HID];
__device__ float g_csd[HID * DM];
__device__ float g_cx [NTOK * DM];

// ---------------- helpers ----------------
__device__ __forceinline__ uint32_t smem_u32(const void* p) {
    uint32_t a;
    asm("{ .reg .u64 t; cvta.to.shared.u64 t, %1; cvt.u32.u64 %0, t; }" : "=r"(a) : "l"(p));
    return a;
}
__device__ __forceinline__ unsigned f2tf(float f) {
    unsigned u; asm("cvt.rna.tf32.f32 %0, %1;" : "=r"(u) : "f"(f)); return u;
}
__device__ __forceinline__ void cp16(uint32_t dst, const void* src) {
    asm volatile("cp.async.cg.shared.global [%0], [%1], 16;" :: "r"(dst), "l"(src));
}
#define CP_COMMIT() asm volatile("cp.async.commit_group;" ::: "memory")
#define CP_WAIT2()  asm volatile("cp.async.wait_group 2;" ::: "memory")

__device__ __forceinline__ void mma_tf32(float c[4], const unsigned a[4], const unsigned b[2]) {
    asm volatile(
        "mma.sync.aligned.m16n8k8.row.col.f32.tf32.tf32.f32 "
        "{%0,%1,%2,%3},{%4,%5,%6,%7},{%8,%9},{%0,%1,%2,%3};"
        : "+f"(c[0]), "+f"(c[1]), "+f"(c[2]), "+f"(c[3])
        : "r"(a[0]), "r"(a[1]), "r"(a[2]), "r"(a[3]), "r"(b[0]), "r"(b[1]));
}

// ---------------- kernel: tf32 pre-rounding ----------------
__global__ void __launch_bounds__(256) cvt_kernel(const float4* __restrict__ src, int which, int n4) {
    float4* dst;
    switch (which) {
        case 0: dst = (float4*)g_cwg; break;
        case 1: dst = (float4*)g_cwu; break;
        case 2: dst = (float4*)g_cwd; break;
        case 3: dst = (float4*)g_csg; break;
        case 4: dst = (float4*)g_csu; break;
        case 5: dst = (float4*)g_csd; break;
        default: dst = (float4*)g_cx; break;
    }
    int i = blockIdx.x * blockDim.x + threadIdx.x;
    if (i >= n4) return;
    float4 v = src[i];
    uint4 t; t.x = f2tf(v.x); t.y = f2tf(v.y); t.z = f2tf(v.z); t.w = f2tf(v.w);
    ((uint4*)dst)[i] = t;
}

// ---------------- kernel: zero counters ----------------
__global__ void zero_kernel() { if (threadIdx.x < NE) g_cnt[threadIdx.x] = 0; }

// ---------------- kernel: router (one warp per token) ----------------
__global__ void __launch_bounds__(256) router_kernel(const float* __restrict__ x,
                                                     const float* __restrict__ rw) {
    __shared__ float srw[NE * DM];
    for (int i = threadIdx.x; i < NE * DM; i += blockDim.x) srw[i] = rw[i];
    __syncthreads();
    int warp = (blockIdx.x * blockDim.x + threadIdx.x) >> 5;
    int lane = threadIdx.x & 31;
    if (warp >= NTOK) return;
    const float* xr = x + (size_t)warp * DM;
    float acc[NE];
#pragma unroll
    for (int e = 0; e < NE; e++) acc[e] = 0.f;
    for (int k = lane; k < DM; k += 32) {
        float xv = xr[k];
#pragma unroll
        for (int e = 0; e < NE; e++) acc[e] += xv * srw[e * DM + k];
    }
#pragma unroll
    for (int e = 0; e < NE; e++) {
#pragma unroll
        for (int o = 16; o > 0; o >>= 1) acc[e] += __shfl_xor_sync(0xffffffffu, acc[e], o);
    }
    if (lane == 0) {
        int i1 = 0; float v1 = acc[0];
#pragma unroll
        for (int e = 1; e < NE; e++) if (acc[e] > v1) { v1 = acc[e]; i1 = e; }
        int i2 = -1; float v2 = -1e30f;
#pragma unroll
        for (int e = 0; e < NE; e++) if (e != i1 && acc[e] > v2) { v2 = acc[e]; i2 = e; }
        float w1 = 1.f / (1.f + expf(v2 - v1));
        float w2 = 1.f - w1;
        int p1 = atomicAdd(&g_cnt[i1], 1);
        g_tok[i1 * NTOK + p1] = warp; g_wt[i1 * NTOK + p1] = w1; g_dst[i1 * NTOK + p1] = warp * 3 + 0;
        int p2 = atomicAdd(&g_cnt[i2], 1);
        g_tok[i2 * NTOK + p2] = warp; g_wt[i2 * NTOK + p2] = w2; g_dst[i2 * NTOK + p2] = warp * 3 + 1;
    }
}

// ---------------- kernel: offsets scan ----------------
__global__ void scan_kernel() {
    if (threadIdx.x == 0) {
        int s = 0;
        for (int e = 0; e < NE; e++) { g_off[e] = s; s += g_cnt[e]; }
        g_off[NE] = s;
    }
}

// ============================================================================
// up kernel: cp.async 4-stage pipeline, fused gate/up, SiLU*u epilogue.
// Warp tile 32 (m) x 32 (n) per matrix, both matrices per warp.
// ============================================================================
__global__ void __launch_bounds__(256, 2) up_kernel() {
    int grp = blockIdx.z;
    int cnt, hbase;
    const float *pg, *pu;
    if (grp < NE) {
        cnt = g_cnt[grp]; hbase = g_off[grp];
        pg = g_cwg + (size_t)grp * DM * HID;
        pu = g_cwu + (size_t)grp * DM * HID;
    } else { cnt = NTOK; hbase = 16384; pg = g_csg; pu = g_csu; }
    int mt0 = blockIdx.x * BM;
    if (mt0 >= cnt) return;
    int n0 = blockIdx.y * 64;

    extern __shared__ __align__(16) char smem[];
    uint32_t sb = smem_u32(smem);
    int tid = threadIdx.x;

    // ---- cp.async source setup ----
    // A: 2 chunks/thread: rows (tid>>2) and (tid>>2)+64, 16B at k-offset (tid&3)*4
    int arow0 = tid >> 2, arow1 = arow0 + 64;
    int akc = (tid & 3) * 4;
    int lr0 = mt0 + arow0; if (lr0 >= cnt) lr0 = mt0;
    int lr1 = mt0 + arow1; if (lr1 >= cnt) lr1 = mt0;
    int tok0 = (grp < NE) ? g_tok[grp * NTOK + lr0] : lr0;
    int tok1 = (grp < NE) ? g_tok[grp * NTOK + lr1] : lr1;
    const float* asrc0 = g_cx + (size_t)tok0 * DM + akc;
    const float* asrc1 = g_cx + (size_t)tok1 * DM + akc;
    uint32_t adst0 = (uint32_t)(arow0 * UP_SA * 4 + akc * 4);
    uint32_t adst1 = (uint32_t)(arow1 * UP_SA * 4 + akc * 4);
    // B: krow = tid>>4 (0..15), col chunk (tid&15)*4
    int bkr = tid >> 4, bnc = (tid & 15) * 4;
    const float* bgsrc = pg + (size_t)bkr * HID + n0 + bnc;
    const float* busrc = pu + (size_t)bkr * HID + n0 + bnc;
    uint32_t bdst = (uint32_t)(bkr * UP_SB * 4 + bnc * 4);

    const int NKT = DM / BK;   // 64
    auto issue = [&](int kt) {
        uint32_t st = sb + (uint32_t)(kt & 3) * UP_ST;
        size_t k0 = (size_t)kt * BK;
        cp16(st + UP_A_OFF + adst0, asrc0 + k0);
        cp16(st + UP_A_OFF + adst1, asrc1 + k0);
        cp16(st + UP_BG_OFF + bdst, bgsrc + k0 * HID);
        cp16(st + UP_BU_OFF + bdst, busrc + k0 * HID);
    };

    issue(0); CP_COMMIT();
    issue(1); CP_COMMIT();
    issue(2); CP_COMMIT();

    int warp = tid >> 5, lane = tid & 31;
    int wm = (warp & 3) * 32;
    int wn = (warp >> 2) * 32;
    int gid = lane >> 2, tig = lane & 3;

    float accG[2][4][4], accU[2][4][4];
#pragma unroll
    for (int a = 0; a < 2; a++)
#pragma unroll
        for (int b = 0; b < 4; b++)
#pragma unroll
            for (int c = 0; c < 4; c++) { accG[a][b][c] = 0.f; accU[a][b][c] = 0.f; }

    for (int kt = 0; kt < NKT; kt++) {
        CP_WAIT2();
        __syncthreads();
        if (kt + 3 < NKT) issue(kt + 3);
        CP_COMMIT();
        const unsigned* sA  = (const unsigned*)(smem + (size_t)(kt & 3) * UP_ST + UP_A_OFF);
        const unsigned* sBg = (const unsigned*)(smem + (size_t)(kt & 3) * UP_ST + UP_BG_OFF);
        const unsigned* sBu = (const unsigned*)(smem + (size_t)(kt & 3) * UP_ST + UP_BU_OFF);
#pragma unroll
        for (int ks = 0; ks < 2; ks++) {
            int k0 = ks * 8;
            unsigned af[2][4];
#pragma unroll
            for (int mt = 0; mt < 2; mt++) {
                int rb = wm + mt * 16 + gid;
                af[mt][0] = sA[rb * UP_SA + k0 + tig];
                af[mt][1] = sA[(rb + 8) * UP_SA + k0 + tig];
                af[mt][2] = sA[rb * UP_SA + k0 + 4 + tig];
                af[mt][3] = sA[(rb + 8) * UP_SA + k0 + 4 + tig];
            }
#pragma unroll
            for (int nt = 0; nt < 4; nt++) {
                int cb = wn + nt * 8 + gid;
                unsigned bg[2], bu[2];
                bg[0] = sBg[(k0 + tig) * UP_SB + cb];
                bg[1] = sBg[(k0 + 4 + tig) * UP_SB + cb];
                bu[0] = sBu[(k0 + tig) * UP_SB + cb];
                bu[1] = sBu[(k0 + 4 + tig) * UP_SB + cb];
#pragma unroll
                for (int mt = 0; mt < 2; mt++) {
                    mma_tf32(accG[mt][nt], af[mt], bg);
                    mma_tf32(accU[mt][nt], af[mt], bu);
                }
            }
        }
    }

    // epilogue: h = silu(g)*u, rounded to tf32 for the down GEMM
#pragma unroll
    for (int mt = 0; mt < 2; mt++) {
#pragma unroll
        for (int i = 0; i < 4; i++) {
            int row = wm + mt * 16 + gid + ((i & 2) ? 8 : 0);
            int lr = mt0 + row;
            if (lr >= cnt) continue;
            size_t base = (size_t)(hbase + lr) * HID + n0 + wn;
#pragma unroll
            for (int nt = 0; nt < 4; nt++) {
                float g = accG[mt][nt][i], u = accU[mt][nt][i];
                float h = g * u / (1.f + __expf(-g));
                g_h[base + nt * 8 + tig * 2 + (i & 1)] = __uint_as_float(f2tf(h));
            }
        }
    }
}

// ============================================================================
// down kernel: cp.async 4-stage, warp tile 32 (m) x 64 (n), BN=128.
// ============================================================================
__global__ void __launch_bounds__(256, 2) down_kernel() {
    int grp = blockIdx.z;
    int cnt, hbase;
    const float* pd;
    if (grp < NE) { cnt = g_cnt[grp]; hbase = g_off[grp]; pd = g_cwd + (size_t)grp * HID * DM; }
    else          { cnt = NTOK;       hbase = 16384;      pd = g_csd; }
    int mt0 = blockIdx.x * BM;
    if (mt0 >= cnt) return;
    int n0 = blockIdx.y * 128;

    extern __shared__ __align__(16) char smem[];
    uint32_t sb = smem_u32(smem);
    int tid = threadIdx.x;

    int arow0 = tid >> 2, arow1 = arow0 + 64;
    int akc = (tid & 3) * 4;
    int lr0 = mt0 + arow0; if (lr0 >= cnt) lr0 = mt0;
    int lr1 = mt0 + arow1; if (lr1 >= cnt) lr1 = mt0;
    const float* asrc0 = g_h + (size_t)(hbase + lr0) * HID + akc;
    const float* asrc1 = g_h + (size_t)(hbase + lr1) * HID + akc;
    uint32_t adst0 = (uint32_t)(arow0 * DN_SA * 4 + akc * 4);
    uint32_t adst1 = (uint32_t)(arow1 * DN_SA * 4 + akc * 4);
    // B: 16 rows x 128 cols in 2 passes: krow = (tid>>5)+8p, col chunk (tid&31)*4
    int bkr = tid >> 5, bnc = (tid & 31) * 4;
    const float* bsrc = pd + (size_t)bkr * DM + n0 + bnc;
    uint32_t bdst = (uint32_t)(bkr * DN_SB * 4 + bnc * 4);

    const int NKT = HID / BK;  // 256
    auto issue = [&](int kt) {
        uint32_t st = sb + (uint32_t)(kt & 3) * DN_ST;
        size_t k0 = (size_t)kt * BK;
        cp16(st + DN_A_OFF + adst0, asrc0 + k0);
        cp16(st + DN_A_OFF + adst1, asrc1 + k0);
        cp16(st + DN_B_OFF + bdst,               bsrc + k0 * DM);
        cp16(st + DN_B_OFF + bdst + 8 * DN_SB * 4, bsrc + (k0 + 8) * DM);
    };

    issue(0); CP_COMMIT();
    issue(1); CP_COMMIT();
    issue(2); CP_COMMIT();

    int warp = tid >> 5, lane = tid & 31;
    int wm = (warp & 3) * 32;
    int wn = (warp >> 2) * 64;
    int gid = lane >> 2, tig = lane & 3;

    float acc[2][8][4];
#pragma unroll
    for (int a = 0; a < 2; a++)
#pragma unroll
        for (int b = 0; b < 8; b++)
#pragma unroll
            for (int c = 0; c < 4; c++) acc[a][b][c] = 0.f;

    for (int kt = 0; kt < NKT; kt++) {
        CP_WAIT2();
        __syncthreads();
        if (kt + 3 < NKT) issue(kt + 3);
        CP_COMMIT();
        const unsigned* sA = (const unsigned*)(smem + (size_t)(kt & 3) * DN_ST + DN_A_OFF);
        const unsigned* sB = (const unsigned*)(smem + (size_t)(kt & 3) * DN_ST + DN_B_OFF);
#pragma unroll
        for (int ks = 0; ks < 2; ks++) {
            int k0 = ks * 8;
            unsigned af[2][4];
#pragma unroll
            for (int mt = 0; mt < 2; mt++) {
                int rb = wm + mt * 16 + gid;
                af[mt][0] = sA[rb * DN_SA + k0 + tig];
                af[mt][1] = sA[(rb + 8) * DN_SA + k0 + tig];
                af[mt][2] = sA[rb * DN_SA + k0 + 4 + tig];
                af[mt][3] = sA[(rb + 8) * DN_SA + k0 + 4 + tig];
            }
#pragma unroll
            for (int nt = 0; nt < 8; nt++) {
                int cb = wn + nt * 8 + gid;
                unsigned bf[2];
                bf[0] = sB[(k0 + tig) * DN_SB + cb];
                bf[1] = sB[(k0 + 4 + tig) * DN_SB + cb];
#pragma unroll
                for (int mt = 0; mt < 2; mt++) mma_tf32(acc[mt][nt], af[mt], bf);
            }
        }
    }

    // epilogue: y[dst] = wt * acc
    int dsts[4]; float wts[4]; int valid[4];
    int rws[4] = { wm + gid, wm + gid + 8, wm + 16 + gid, wm + 24 + gid };
#pragma unroll
    for (int j = 0; j < 4; j++) {
        int lr = mt0 + rws[j];
        valid[j] = (lr < cnt);
        int lc = valid[j] ? lr : mt0;
        if (grp < NE) { int q = grp * NTOK + lc; dsts[j] = g_dst[q]; wts[j] = g_wt[q]; }
        else          { dsts[j] = lc * 3 + 2;    wts[j] = 1.f; }
    }
#pragma unroll
    for (int mt = 0; mt < 2; mt++)
#pragma unroll
        for (int i = 0; i < 4; i++) {
            int j = mt * 2 + ((i & 2) ? 1 : 0);
            if (!valid[j]) continue;
#pragma unroll
            for (int nt = 0; nt < 8; nt++)
                g_y[(size_t)dsts[j] * DM + n0 + wn + nt * 8 + tig * 2 + (i & 1)] = wts[j] * acc[mt][nt][i];
        }
}

// ---------------- combine ----------------
__global__ void combine_kernel(float* __restrict__ out) {
    int i = blockIdx.x * blockDim.x + threadIdx.x;
    if (i >= NTOK * DM) return;
    int n = i / DM, c = i % DM;
    size_t b = (size_t)n * 3 * DM + c;
    out[i] = g_y[b] + g_y[b + DM] + g_y[b + 2 * DM];
}

// ---------------- launch ----------------
extern "C" void kernel_launch(void* const* d_in, const int* in_sizes, int n_in,
                              void* d_out, int out_size) {
    const float* x   = (const float*)d_in[0];
    const float* rw  = (const float*)d_in[1];
    const float* wg  = (const float*)d_in[2];
    const float* wu  = (const float*)d_in[3];
    const float* wd  = (const float*)d_in[4];
    const float* swg = (const float*)d_in[5];
    const float* swu = (const float*)d_in[6];
    const float* swd = (const float*)d_in[7];
    float* out = (float*)d_out;

    const int UP_SMEM = STAGES * UP_ST;   // 77824
    const int DN_SMEM = STAGES * DN_ST;   // 75776
    cudaFuncSetAttribute(up_kernel,   cudaFuncAttributeMaxDynamicSharedMemorySize, UP_SMEM);
    cudaFuncSetAttribute(down_kernel, cudaFuncAttributeMaxDynamicSharedMemorySize, DN_SMEM);

    // tf32 pre-rounding of weights + x
    const int RW = NE * DM * HID / 4;        // 7340032 quads per routed weight
    const int SW = DM * HID / 4;             // 1048576 quads per shared weight
    const int XW = NTOK * DM / 4;            // 2097152 quads
    cvt_kernel<<<(RW + 255) / 256, 256>>>((const float4*)wg,  0, RW);
    cvt_kernel<<<(RW + 255) / 256, 256>>>((const float4*)wu,  1, RW);
    cvt_kernel<<<(RW + 255) / 256, 256>>>((const float4*)wd,  2, RW);
    cvt_kernel<<<(SW + 255) / 256, 256>>>((const float4*)swg, 3, SW);
    cvt_kernel<<<(SW + 255) / 256, 256>>>((const float4*)swu, 4, SW);
    cvt_kernel<<<(SW + 255) / 256, 256>>>((const float4*)swd, 5, SW);
    cvt_kernel<<<(XW + 255) / 256, 256>>>((const float4*)x,   6, XW);

    zero_kernel<<<1, 32>>>();
    router_kernel<<<NTOK / 8, 256>>>(x, rw);
    scan_kernel<<<1, 32>>>();

    dim3 gu(NTOK / BM, HID / 64, 8);    // (64, 64, 8)
    up_kernel<<<gu, 256, UP_SMEM>>>();

    dim3 gd(NTOK / BM, DM / 128, 8);    // (64, 8, 8)
    down_kernel<<<gd, 256, DN_SMEM>>>();

    combine_kernel<<<(NTOK * DM) / 256, 256>>>(out);
}